// round 10
// baseline (speedup 1.0000x reference)
#include <cuda_runtime.h>

#define L      2048
#define BATCH  512
#define NDIM   128

#define TT 64
#define BB 64
#define TS 64
#define US 66
#define CH 64          // staged rows per chunk in h-pipeline (32 KB)
#define CHS 8          // s-tiles per conv chunk (split-K)

typedef unsigned long long u64;

// ---------------- scratch (__device__ globals, allocation-free) ----------------
__device__ __align__(16) float g_S[2][NDIM * NDIM];  // A^(2^k) chain, ping-pong
__device__ __align__(16) float g_R[2][NDIM * NDIM];  // (A^(64*2^k))^T chain
__device__ __align__(16) float g_W[64 * NDIM];       // w_j = (A^T)^j B
__device__ __align__(16) float g_Y[32 * NDIM];       // y_i = A^(64 i) C
__device__ float g_h[L];                             // h_n = B A^n C
__device__ __align__(16) float g_part[4][BATCH * L]; // split-K partials (16 MB)

// ---------------------------------------------------------------------------
// 256-thread block-cooperative column dot: sum_k shrow[k] * M[k*NDIM + col].
// Two rows/vectors per block share one staged tile; 8 warps -> 2 per SMSP.
// Must be reached by ALL 256 threads (contains __syncthreads).
// ---------------------------------------------------------------------------
__device__ __forceinline__ float staged_dot256(const float* __restrict__ M,
                                               const float* shrow,
                                               float* tile, int tid, int col)
{
    float a0 = 0.f, a1 = 0.f, a2 = 0.f, a3 = 0.f;
#pragma unroll
    for (int kk = 0; kk < NDIM; kk += CH) {
        __syncthreads();
        const float4* src = (const float4*)(M + kk * NDIM);
        float4* dst = (float4*)tile;
#pragma unroll
        for (int p = 0; p < (CH * NDIM / 4) / 256; ++p)    // 8 indep float4
            dst[p * 256 + tid] = src[p * 256 + tid];
        __syncthreads();
#pragma unroll
        for (int q = 0; q < CH; q += 4) {
            a0 += shrow[kk + q + 0] * tile[(q + 0) * NDIM + col];
            a1 += shrow[kk + q + 1] * tile[(q + 1) * NDIM + col];
            a2 += shrow[kk + q + 2] * tile[(q + 2) * NDIM + col];
            a3 += shrow[kk + q + 3] * tile[(q + 3) * NDIM + col];
        }
    }
    return (a0 + a1) + (a2 + a3);
}

// Stage k of W phase (k=0..5). 256 threads, 2 rows/vectors per block.
//   blocks [0,64): squaring  S_{k+1} = S_k S_k  (k==5: write transposed -> R_0)
//   blocks [64,..): expand   w_{2^k+j} = (A^T)^{2^k} w_j, 2 j's per block
//   k==0, block 64, half 0: seeds g_W[0]=B, g_Y[0]=C.
__global__ __launch_bounds__(256) void stageW_kernel(int k,
                                                     const float* __restrict__ Af,
                                                     const float* __restrict__ Bf,
                                                     const float* __restrict__ Cf)
{
    __shared__ float sh[2][NDIM];
    __shared__ __align__(16) float tile[CH * NDIM];
    const int tid  = threadIdx.x;
    const int half = tid >> 7;
    const int col  = tid & 127;
    const int m    = 1 << k;
    const float* M = (k == 0) ? Af : g_S[k & 1];

    if (blockIdx.x < 64) {                     // ---- squaring, rows 2b, 2b+1 ----
        const int r = 2 * blockIdx.x + half;
        sh[half][col] = M[r * NDIM + col];
        float acc = staged_dot256(M, sh[half], tile, tid, col);
        if (k == 5) g_R[0][col * NDIM + r] = acc;          // R_0 = (A^64)^T
        else        g_S[(k + 1) & 1][r * NDIM + col] = acc;
    } else {                                   // ---- expand W, j = j0, j0+1 ----
        const int j  = 2 * (blockIdx.x - 64) + half;
        const int jj = (j < m) ? j : m - 1;    // clamp for safe load
        if (k == 0) {
            sh[half][col] = Bf[col];
            if (half == 0) { g_W[col] = Bf[col]; g_Y[col] = Cf[col]; }
        } else {
            sh[half][col] = g_W[jj * NDIM + col];
        }
        float acc = staged_dot256(M, sh[half], tile, tid, col);
        if (j < m) g_W[(m + j) * NDIM + col] = acc;
    }
}

// Stage k of Y phase (k=0..4). 256 threads, 2 rows/vectors per block.
//   k<4 : blocks [0,64) square R_k; blocks [64,..) expand Y (2 per block)
//   k==4: all blocks expand (base 0).
__global__ __launch_bounds__(256) void stageY_kernel(int k)
{
    __shared__ float sh[2][NDIM];
    __shared__ __align__(16) float tile[CH * NDIM];
    const int tid  = threadIdx.x;
    const int half = tid >> 7;
    const int col  = tid & 127;
    const int m    = 1 << k;
    const float* R = g_R[k & 1];
    const int base = (k < 4) ? 64 : 0;

    if (k < 4 && blockIdx.x < 64) {            // ---- squaring R ----
        const int r = 2 * blockIdx.x + half;
        sh[half][col] = R[r * NDIM + col];
        float acc = staged_dot256(R, sh[half], tile, tid, col);
        g_R[(k + 1) & 1][r * NDIM + col] = acc;
    } else {                                   // ---- expand Y ----
        const int j  = 2 * ((int)blockIdx.x - base) + half;
        const int jj = (j < m) ? j : m - 1;
        sh[half][col] = g_Y[jj * NDIM + col];
        float acc = staged_dot256(R, sh[half], tile, tid, col);
        if (j < m) g_Y[(m + j) * NDIM + col] = acc;
    }
}

// h[64*i + j] = w_j . y_i   (block = i, 256 threads, 4 lanes per dot)
__global__ void hdot_kernel()
{
    __shared__ float ys[NDIM];
    const int i = blockIdx.x;
    const int tid = threadIdx.x;
    if (tid < NDIM) ys[tid] = g_Y[i * NDIM + tid];
    __syncthreads();
    const int j = tid >> 2, q = tid & 3;
    const float* __restrict__ w = &g_W[j * NDIM + q * 32];
    const float* __restrict__ y = &ys[q * 32];
    float p0 = 0.f, p1 = 0.f;
#pragma unroll
    for (int c = 0; c < 32; c += 2) { p0 += w[c] * y[c]; p1 += w[c + 1] * y[c + 1]; }
    float p = p0 + p1;
    p += __shfl_xor_sync(0xFFFFFFFFu, p, 1);
    p += __shfl_xor_sync(0xFFFFFFFFu, p, 2);
    if (q == 0) g_h[i * 64 + j] = p;
}

// ---------------------------------------------------------------------------
// Packed f32x2 helpers
// ---------------------------------------------------------------------------
__device__ __forceinline__ void ffma2(u64& d, u64 a, u64 b)
{
    asm("fma.rn.f32x2 %0, %1, %2, %0;" : "+l"(d) : "l"(a), "l"(b));
}
__device__ __forceinline__ u64 splat2(float x)
{
    u64 r; asm("mov.b64 %0, {%1, %1};" : "=l"(r) : "f"(x)); return r;
}
__device__ __forceinline__ void unpack2(u64 v, float& lo, float& hi)
{
    asm("mov.b64 {%0, %1}, %2;" : "=f"(lo), "=f"(hi) : "l"(v));
}

// ---------------------------------------------------------------------------
// Split-K causal Toeplitz conv: each block = (t-tile, s-chunk, b-slice);
// partial -> g_part[chunk]. 640 balanced blocks, ~4 co-resident per SM.
// ---------------------------------------------------------------------------
__global__ __launch_bounds__(128) void conv_kernel(const float* __restrict__ u)
{
    __shared__ __align__(16) float Us[TS][US];   // [ss][bb]
    __shared__ float hsArr[132];
    float* hsp = hsArr + 4;

    int bs = blockIdx.x & 7;
    int q  = blockIdx.x >> 3;            // 0..79
    int tileT = 31;
    while (true) { int n = (tileT + 8) >> 3; if (q < n) break; q -= n; --tileT; }
    const int chunk = q;                 // 0..3
    const int t0    = tileT * TT;
    const int b0    = bs * BB;
    const int stLo  = chunk * CHS;
    const int stHi  = min(stLo + CHS - 1, tileT);

    const int tid = threadIdx.x;
    const int tx  = tid & 7;
    const int ty  = tid >> 3;
    const int tt0 = tx * 8;
    const int bb0 = ty * 4;

    u64 acc2[8][2];
#pragma unroll
    for (int r = 0; r < 8; ++r) { acc2[r][0] = 0ull; acc2[r][1] = 0ull; }

    if (tid < 4) hsArr[tid] = 0.0f;      // guards hsp[-4..-1]

    for (int st = stLo; st <= stHi; ++st) {
        const int s0 = st * TS;
        __syncthreads();
        {   // h window: hsp[d] = h[t0-s0-63+d], zero OOB
            int g = t0 - s0 - 63 + tid;
            hsp[tid] = (g >= 0 && g < L) ? g_h[g] : 0.0f;
        }
#pragma unroll
        for (int p = 0; p < 32; ++p) {   // coalesced LDG fill
            int f  = p * 128 + tid;
            int bb = f >> 6;
            int ss = f & 63;
            Us[ss][bb] = u[(size_t)(b0 + bb) * L + (s0 + ss)];
        }
        __syncthreads();

        u64 w2[8];
#pragma unroll
        for (int r = 0; r < 8; ++r) w2[r] = splat2(hsp[tt0 + 63 + r]);

#pragma unroll
        for (int ss = 0; ss < TS; ++ss) {
            u64 u01 = *(const u64*)&Us[ss][bb0];
            u64 u23 = *(const u64*)&Us[ss][bb0 + 2];
#pragma unroll
            for (int r = 0; r < 8; ++r) {
                ffma2(acc2[r][0], u01, w2[r]);
                ffma2(acc2[r][1], u23, w2[r]);
            }
            float nw = hsp[tt0 + 62 - ss];
#pragma unroll
            for (int r = 7; r > 0; --r) w2[r] = w2[r - 1];
            w2[0] = splat2(nw);
        }
    }

    float* __restrict__ part = g_part[chunk];
#pragma unroll
    for (int r = 0; r < 8; ++r) {
        const int t = t0 + tt0 + r;
#pragma unroll
        for (int p = 0; p < 2; ++p) {
            float lo, hi;
            unpack2(acc2[r][p], lo, hi);
            const int b = b0 + bb0 + 2 * p;
            part[(size_t)b * L + t]       = lo;
            part[(size_t)(b + 1) * L + t] = hi;
        }
    }
}

// ---------------------------------------------------------------------------
// Reduce: out = f_t * sum_{c<nch(t)} part[c] + D*u.  float4 over t.
// ---------------------------------------------------------------------------
__global__ __launch_bounds__(256) void reduce_kernel(const float* __restrict__ u,
                                                     const float* __restrict__ Dp,
                                                     float* __restrict__ out)
{
    const int idx = blockIdx.x * 256 + threadIdx.x;   // float4 index
    const int e0  = idx * 4;
    const int t   = e0 & (L - 1);                     // time index of lane .x
    const int nch = ((t >> 6) + 8) >> 3;              // ceil((tileT+1)/8)

    float4 s = ((const float4*)g_part[0])[idx];
    if (nch > 1) { float4 v = ((const float4*)g_part[1])[idx];
                   s.x += v.x; s.y += v.y; s.z += v.z; s.w += v.w; }
    if (nch > 2) { float4 v = ((const float4*)g_part[2])[idx];
                   s.x += v.x; s.y += v.y; s.z += v.z; s.w += v.w; }
    if (nch > 3) { float4 v = ((const float4*)g_part[3])[idx];
                   s.x += v.x; s.y += v.y; s.z += v.z; s.w += v.w; }

    const float Dv = Dp[0];
    float4 uu = ((const float4*)u)[idx];
    float4 o;
    // e0 is a multiple of 4 -> only lane .x can have t==0.
    o.x = ((t == 0) ? 1.0f : 2.0f) * s.x + Dv * uu.x;
    o.y = 2.0f * s.y + Dv * uu.y;
    o.z = 2.0f * s.z + Dv * uu.z;
    o.w = 2.0f * s.w + Dv * uu.w;
    ((float4*)out)[idx] = o;
}

// ---------------------------------------------------------------------------
extern "C" void kernel_launch(void* const* d_in, const int* in_sizes, int n_in,
                              void* d_out, int out_size)
{
    const float* u  = (const float*)d_in[0];  // (512, 2048)
    const float* A  = (const float*)d_in[1];  // (128, 128)
    const float* B  = (const float*)d_in[2];  // (128,)
    const float* Cd = (const float*)d_in[3];  // (128,)
    const float* Dd = (const float*)d_in[4];  // (1,)
    float* out = (float*)d_out;               // (512, 2048)

    for (int k = 0; k <= 5; ++k) {
        int nexp = ((1 << k) + 1) >> 1;               // 2 vectors per block
        stageW_kernel<<<64 + nexp, 256>>>(k, A, B, Cd);
    }
    for (int k = 0; k <= 4; ++k) {
        int nexp = ((1 << k) + 1) >> 1;
        int grid = (k < 4) ? 64 + nexp : nexp;
        stageY_kernel<<<grid, 256>>>(k);
    }
    hdot_kernel<<<32, 256>>>();

    conv_kernel<<<640, 128>>>(u);                     // split-K partials
    reduce_kernel<<<(BATCH * L / 4) / 256, 256>>>(u, Dd, out);
}

// round 11
// speedup vs baseline: 1.0384x; 1.0384x over previous
#include <cuda_runtime.h>

#define L      2048
#define BATCH  512
#define NDIM   128

#define TT 64
#define BB 64
#define TS 64
#define US 66
#define CH 64          // staged rows per chunk in h-pipeline (32 KB)
#define CHS 8          // s-tiles per conv chunk (split-K)

typedef unsigned long long u64;

// ---------------- scratch (__device__ globals, allocation-free) ----------------
__device__ __align__(16) float g_S[2][NDIM * NDIM];  // A^(2^k) chain, ping-pong
__device__ __align__(16) float g_R[2][NDIM * NDIM];  // (A^(64*2^k))^T chain
__device__ __align__(16) float g_W[64 * NDIM];       // w_j = (A^T)^j B
__device__ __align__(16) float g_Y[32 * NDIM];       // y_i = A^(64 i) C
__device__ float g_h[L];                             // h_n = B A^n C
__device__ __align__(16) float g_part[4][BATCH * L]; // split-K partials (16 MB)

// ---------------------------------------------------------------------------
// 512-thread, 4-way k-split column dot: result[col] = sum_k sh[k]*M[k*NDIM+col].
// part = tid>>7 handles rows 4q+part of each staged 64-row chunk -> per-thread
// chain is 32 accumulate iterations instead of 128.
// Returns the partial for this part; caller combines via comb[].
// ---------------------------------------------------------------------------
__device__ __forceinline__ float split_dot(const float* __restrict__ M,
                                           const float* sh, float* tile,
                                           int tid, int col, int part)
{
    float a0 = 0.f, a1 = 0.f, a2 = 0.f, a3 = 0.f;
#pragma unroll
    for (int kk = 0; kk < NDIM; kk += CH) {
        __syncthreads();
        const float4* src = (const float4*)(M + kk * NDIM);
        float4* dst = (float4*)tile;
#pragma unroll
        for (int p = 0; p < (CH * NDIM / 4) / 512; ++p)    // 4 indep float4
            dst[p * 512 + tid] = src[p * 512 + tid];
        __syncthreads();
#pragma unroll
        for (int q = 0; q < 16; q += 4) {
            a0 += sh[kk + 4 * (q + 0) + part] * tile[(4 * (q + 0) + part) * NDIM + col];
            a1 += sh[kk + 4 * (q + 1) + part] * tile[(4 * (q + 1) + part) * NDIM + col];
            a2 += sh[kk + 4 * (q + 2) + part] * tile[(4 * (q + 2) + part) * NDIM + col];
            a3 += sh[kk + 4 * (q + 3) + part] * tile[(4 * (q + 3) + part) * NDIM + col];
        }
    }
    return (a0 + a1) + (a2 + a3);
}

// Stage k of W phase (k=0..5). 512 threads, 1 row/vector per block.
//   blocks [0,128): squaring S_{k+1} = S_k S_k (k==5: write transposed -> R_0)
//   blocks [128,128+2^k): expand w_{2^k+j} = (A^T)^{2^k} w_j
//   k==0: expand block also seeds g_W[0]=B, g_Y[0]=C.
__global__ __launch_bounds__(512) void stageW_kernel(int k,
                                                     const float* __restrict__ Af,
                                                     const float* __restrict__ Bf,
                                                     const float* __restrict__ Cf)
{
    __shared__ float sh[NDIM];
    __shared__ __align__(16) float tile[CH * NDIM];
    __shared__ float comb[3 * NDIM];
    const int tid  = threadIdx.x;
    const int col  = tid & 127;
    const int part = tid >> 7;
    const int m    = 1 << k;
    const float* M = (k == 0) ? Af : g_S[k & 1];
    const bool sq  = blockIdx.x < 128;

    if (sq) {
        if (part == 0) sh[col] = M[blockIdx.x * NDIM + col];
    } else {
        const int j = blockIdx.x - 128;
        if (part == 0) sh[col] = (k == 0) ? Bf[col] : g_W[j * NDIM + col];
        if (k == 0 && part == 1) g_W[col] = Bf[col];
        if (k == 0 && part == 2) g_Y[col] = Cf[col];
    }

    float partial = split_dot(M, sh, tile, tid, col, part);

    __syncthreads();
    if (part) comb[(part - 1) * NDIM + col] = partial;
    __syncthreads();
    if (part == 0) {
        float acc = partial + comb[col] + comb[NDIM + col] + comb[2 * NDIM + col];
        if (sq) {
            if (k == 5) g_R[0][col * NDIM + blockIdx.x] = acc;   // R_0 = (A^64)^T
            else        g_S[(k + 1) & 1][blockIdx.x * NDIM + col] = acc;
        } else {
            g_W[(m + (int)blockIdx.x - 128) * NDIM + col] = acc;
        }
    }
}

// Stage k of Y phase (k=0..4). 512 threads, 1 row/vector per block.
//   k<4 : blocks [0,128) square R_k; blocks [128,128+2^k) expand Y.
//   k==4: blocks [0,16) expand y_{16+b} AND compute h rows; blocks [16,32)
//         compute h rows for i<16 (hdot merged into this launch).
__global__ __launch_bounds__(512) void stageY_kernel(int k)
{
    __shared__ float sh[NDIM];
    __shared__ __align__(16) float tile[CH * NDIM];
    __shared__ float comb[3 * NDIM];
    __shared__ float ys[NDIM];
    const int tid  = threadIdx.x;
    const int col  = tid & 127;
    const int part = tid >> 7;
    const int m    = 1 << k;
    const float* R = g_R[k & 1];
    const bool sq  = (k < 4) && (blockIdx.x < 128);
    const int base = (k < 4) ? 128 : 0;
    const bool hdotOnly = (k == 4) && ((int)blockIdx.x >= 16);

    if (!hdotOnly) {
        const int b = (int)blockIdx.x - base;          // expand index (if !sq)
        if (part == 0) sh[col] = sq ? R[blockIdx.x * NDIM + col]
                                    : g_Y[b * NDIM + col];
        float partial = split_dot(R, sh, tile, tid, col, part);
        __syncthreads();
        if (part) comb[(part - 1) * NDIM + col] = partial;
        __syncthreads();
        if (part == 0) {
            float acc = partial + comb[col] + comb[NDIM + col] + comb[2 * NDIM + col];
            if (sq) {
                g_R[(k + 1) & 1][blockIdx.x * NDIM + col] = acc;
            } else {
                g_Y[(m + b) * NDIM + col] = acc;
                if (k == 4) ys[col] = acc;             // for inline hdot
            }
        }
    } else {
        if (tid < NDIM) ys[tid] = g_Y[((int)blockIdx.x - 16) * NDIM + tid];
    }

    if (k == 4) {                                      // ---- inline hdot ----
        __syncthreads();
        const int i = ((int)blockIdx.x < 16) ? 16 + (int)blockIdx.x
                                             : (int)blockIdx.x - 16;
        const int j = tid >> 3, l = tid & 7;           // 64 j's x 8 lanes
        float p = 0.f;
#pragma unroll
        for (int c = 0; c < 16; ++c)
            p += g_W[j * NDIM + l + 8 * c] * ys[l + 8 * c];
        p += __shfl_xor_sync(0xFFFFFFFFu, p, 4);
        p += __shfl_xor_sync(0xFFFFFFFFu, p, 2);
        p += __shfl_xor_sync(0xFFFFFFFFu, p, 1);
        if (l == 0) g_h[i * 64 + j] = p;
    }
}

// ---------------------------------------------------------------------------
// Packed f32x2 helpers
// ---------------------------------------------------------------------------
__device__ __forceinline__ void ffma2(u64& d, u64 a, u64 b)
{
    asm("fma.rn.f32x2 %0, %1, %2, %0;" : "+l"(d) : "l"(a), "l"(b));
}
__device__ __forceinline__ u64 splat2(float x)
{
    u64 r; asm("mov.b64 %0, {%1, %1};" : "=l"(r) : "f"(x)); return r;
}
__device__ __forceinline__ void unpack2(u64 v, float& lo, float& hi)
{
    asm("mov.b64 {%0, %1}, %2;" : "=f"(lo), "=f"(hi) : "l"(v));
}

// ---------------------------------------------------------------------------
// Split-K causal Toeplitz conv: each block = (t-tile, s-chunk, b-slice);
// partial -> g_part[chunk]. 640 balanced blocks, ~4 co-resident per SM.
// ---------------------------------------------------------------------------
__global__ __launch_bounds__(128) void conv_kernel(const float* __restrict__ u)
{
    __shared__ __align__(16) float Us[TS][US];   // [ss][bb]
    __shared__ float hsArr[132];
    float* hsp = hsArr + 4;

    int bs = blockIdx.x & 7;
    int q  = blockIdx.x >> 3;            // 0..79
    int tileT = 31;
    while (true) { int n = (tileT + 8) >> 3; if (q < n) break; q -= n; --tileT; }
    const int chunk = q;                 // 0..3
    const int t0    = tileT * TT;
    const int b0    = bs * BB;
    const int stLo  = chunk * CHS;
    const int stHi  = min(stLo + CHS - 1, tileT);

    const int tid = threadIdx.x;
    const int tx  = tid & 7;
    const int ty  = tid >> 3;
    const int tt0 = tx * 8;
    const int bb0 = ty * 4;

    u64 acc2[8][2];
#pragma unroll
    for (int r = 0; r < 8; ++r) { acc2[r][0] = 0ull; acc2[r][1] = 0ull; }

    if (tid < 4) hsArr[tid] = 0.0f;      // guards hsp[-4..-1]

    for (int st = stLo; st <= stHi; ++st) {
        const int s0 = st * TS;
        __syncthreads();
        {   // h window: hsp[d] = h[t0-s0-63+d], zero OOB
            int g = t0 - s0 - 63 + tid;
            hsp[tid] = (g >= 0 && g < L) ? g_h[g] : 0.0f;
        }
#pragma unroll
        for (int p = 0; p < 32; ++p) {   // coalesced LDG fill
            int f  = p * 128 + tid;
            int bb = f >> 6;
            int ss = f & 63;
            Us[ss][bb] = u[(size_t)(b0 + bb) * L + (s0 + ss)];
        }
        __syncthreads();

        u64 w2[8];
#pragma unroll
        for (int r = 0; r < 8; ++r) w2[r] = splat2(hsp[tt0 + 63 + r]);

#pragma unroll
        for (int ss = 0; ss < TS; ++ss) {
            u64 u01 = *(const u64*)&Us[ss][bb0];
            u64 u23 = *(const u64*)&Us[ss][bb0 + 2];
#pragma unroll
            for (int r = 0; r < 8; ++r) {
                ffma2(acc2[r][0], u01, w2[r]);
                ffma2(acc2[r][1], u23, w2[r]);
            }
            float nw = hsp[tt0 + 62 - ss];
#pragma unroll
            for (int r = 7; r > 0; --r) w2[r] = w2[r - 1];
            w2[0] = splat2(nw);
        }
    }

    float* __restrict__ part = g_part[chunk];
#pragma unroll
    for (int r = 0; r < 8; ++r) {
        const int t = t0 + tt0 + r;
#pragma unroll
        for (int p = 0; p < 2; ++p) {
            float lo, hi;
            unpack2(acc2[r][p], lo, hi);
            const int b = b0 + bb0 + 2 * p;
            part[(size_t)b * L + t]       = lo;
            part[(size_t)(b + 1) * L + t] = hi;
        }
    }
}

// ---------------------------------------------------------------------------
// Reduce: out = f_t * sum_{c<nch(t)} part[c] + D*u.  float4 over t.
// ---------------------------------------------------------------------------
__global__ __launch_bounds__(256) void reduce_kernel(const float* __restrict__ u,
                                                     const float* __restrict__ Dp,
                                                     float* __restrict__ out)
{
    const int idx = blockIdx.x * 256 + threadIdx.x;   // float4 index
    const int e0  = idx * 4;
    const int t   = e0 & (L - 1);                     // time index of lane .x
    const int nch = ((t >> 6) + 8) >> 3;              // ceil((tileT+1)/8)

    float4 s = ((const float4*)g_part[0])[idx];
    if (nch > 1) { float4 v = ((const float4*)g_part[1])[idx];
                   s.x += v.x; s.y += v.y; s.z += v.z; s.w += v.w; }
    if (nch > 2) { float4 v = ((const float4*)g_part[2])[idx];
                   s.x += v.x; s.y += v.y; s.z += v.z; s.w += v.w; }
    if (nch > 3) { float4 v = ((const float4*)g_part[3])[idx];
                   s.x += v.x; s.y += v.y; s.z += v.z; s.w += v.w; }

    const float Dv = Dp[0];
    float4 uu = ((const float4*)u)[idx];
    float4 o;
    // e0 is a multiple of 4 -> only lane .x can have t==0.
    o.x = ((t == 0) ? 1.0f : 2.0f) * s.x + Dv * uu.x;
    o.y = 2.0f * s.y + Dv * uu.y;
    o.z = 2.0f * s.z + Dv * uu.z;
    o.w = 2.0f * s.w + Dv * uu.w;
    ((float4*)out)[idx] = o;
}

// ---------------------------------------------------------------------------
extern "C" void kernel_launch(void* const* d_in, const int* in_sizes, int n_in,
                              void* d_out, int out_size)
{
    const float* u  = (const float*)d_in[0];  // (512, 2048)
    const float* A  = (const float*)d_in[1];  // (128, 128)
    const float* B  = (const float*)d_in[2];  // (128,)
    const float* Cd = (const float*)d_in[3];  // (128,)
    const float* Dd = (const float*)d_in[4];  // (1,)
    float* out = (float*)d_out;               // (512, 2048)

    for (int k = 0; k <= 5; ++k)
        stageW_kernel<<<128 + (1 << k), 512>>>(k, A, B, Cd);

    for (int k = 0; k <= 4; ++k) {
        int grid = (k < 4) ? 128 + (1 << k) : 32;     // k==4: 16 expand + 16 hdot
        stageY_kernel<<<grid, 512>>>(k);
    }

    conv_kernel<<<640, 128>>>(u);                     // split-K partials
    reduce_kernel<<<(BATCH * L / 4) / 256, 256>>>(u, Dd, out);
}